// round 2
// baseline (speedup 1.0000x reference)
#include <cuda_runtime.h>
#include <math.h>

#define NN   50000
#define EE   400000
#define FULLM 0xffffffffu

// ---------------- device scratch ----------------
__device__ __align__(16) float g_Q[NN * 128];
__device__ __align__(16) float g_K[NN * 128];
__device__ __align__(16) float g_agg[NN * 128];
__device__ __align__(16) float g_WqT[64 * 128];    // [r][j] = Wq[j][r]
__device__ __align__(16) float g_WkT[128 * 128];   // [r][j] = Wk[j][r] (0-63 mem, 64-95 ef, 96-127 time)
__device__ __align__(16) float g_W1T[192 * 512];   // [k][j]
__device__ __align__(16) float g_qc[128];
__device__ int g_cnt[NN];
__device__ int g_off[NN];
__device__ int g_cur[NN];
__device__ int g_eidx[EE];

// ---------------- f32x2 helpers ----------------
__device__ __forceinline__ unsigned long long pk2(float lo, float hi) {
    unsigned long long r;
    asm("mov.b64 %0, {%1, %2};" : "=l"(r) : "f"(lo), "f"(hi));
    return r;
}
__device__ __forceinline__ void fma2(unsigned long long& d, unsigned long long a, unsigned long long b) {
    asm("fma.rn.f32x2 %0, %1, %2, %0;" : "+l"(d) : "l"(a), "l"(b));
}
__device__ __forceinline__ float2 upk2(unsigned long long v) {
    float lo, hi;
    asm("mov.b64 {%0, %1}, %2;" : "=f"(lo), "=f"(hi) : "l"(v));
    return make_float2(lo, hi);
}

// ---------------- setup: transposes + qconst + zero counters ----------------
__global__ void k_prep(const float* __restrict__ Wq, const float* __restrict__ Wk,
                       const float* __restrict__ W1, const float* __restrict__ time_b) {
    int i = blockIdx.x * blockDim.x + threadIdx.x;
    if (i < 192 * 512) { int k = i / 512, j = i % 512; g_W1T[i] = W1[j * 192 + k]; }
    if (i < 128 * 128) { int r = i / 128, j = i % 128; g_WkT[i] = Wk[j * 128 + r]; }
    if (i < 64 * 128)  { int r = i / 128, j = i % 128; g_WqT[i] = Wq[j * 96 + r]; }
    if (i < NN) g_cnt[i] = 0;
    if (i < 128) {
        float s = 0.f;
        for (int t = 0; t < 32; t++) s += Wq[i * 96 + 64 + t] * cosf(__ldg(time_b + t));
        g_qc[i] = s;
    }
}

__global__ void k_count(const int* __restrict__ dst) {
    int e = blockIdx.x * blockDim.x + threadIdx.x;
    if (e < EE) atomicAdd(&g_cnt[dst[e]], 1);
}

__global__ void k_scan() {
    __shared__ int ss[1024];
    int t = threadIdx.x;
    const int CH = (NN + 1023) / 1024;
    int b = t * CH;
    int s = 0;
    for (int i = 0; i < CH; i++) { int idx = b + i; if (idx < NN) s += g_cnt[idx]; }
    ss[t] = s;
    __syncthreads();
    for (int o = 1; o < 1024; o <<= 1) {
        int v = (t >= o) ? ss[t - o] : 0;
        __syncthreads();
        ss[t] += v;
        __syncthreads();
    }
    int pre = t ? ss[t - 1] : 0;
    for (int i = 0; i < CH; i++) {
        int idx = b + i;
        if (idx < NN) { int c = g_cnt[idx]; g_off[idx] = pre; g_cur[idx] = pre; pre += c; }
    }
}

__global__ void k_scatter(const int* __restrict__ dst) {
    int e = blockIdx.x * blockDim.x + threadIdx.x;
    if (e < EE) { int p = atomicAdd(&g_cur[dst[e]], 1); g_eidx[p] = e; }
}

// ---------------- node projections (f32x2, both weight mats in smem) ----------------
__global__ __launch_bounds__(256) void k_node(const float* __restrict__ memory) {
    extern __shared__ float sm[];
    float* sWq = sm;
    float* sWk = sm + 8192;
    for (int i = threadIdx.x; i < 8192; i += 256) { sWq[i] = g_WqT[i]; sWk[i] = g_WkT[i]; }
    __syncthreads();
    int l = threadIdx.x & 31, w = threadIdx.x >> 5;
    int warp = blockIdx.x * 8 + w, stride = gridDim.x * 8;
    for (int node = warp; node < NN; node += stride) {
        float2 m2 = *(const float2*)(memory + node * 64 + 2 * l);
        ulonglong2 qc2 = *(const ulonglong2*)(g_qc + 4 * l);
        unsigned long long aQ0 = qc2.x, aQ1 = qc2.y, aK0 = 0ULL, aK1 = 0ULL;
#pragma unroll 8
        for (int i = 0; i < 32; i++) {
            float va = __shfl_sync(FULLM, m2.x, i);
            float vb = __shfl_sync(FULLM, m2.y, i);
            unsigned long long pa = pk2(va, va), pb = pk2(vb, vb);
            ulonglong2 qa = *(const ulonglong2*)(sWq + (2 * i) * 128 + 4 * l);
            ulonglong2 qb = *(const ulonglong2*)(sWq + (2 * i + 1) * 128 + 4 * l);
            ulonglong2 ka = *(const ulonglong2*)(sWk + (2 * i) * 128 + 4 * l);
            ulonglong2 kb = *(const ulonglong2*)(sWk + (2 * i + 1) * 128 + 4 * l);
            fma2(aQ0, pa, qa.x); fma2(aQ1, pa, qa.y);
            fma2(aQ0, pb, qb.x); fma2(aQ1, pb, qb.y);
            fma2(aK0, pa, ka.x); fma2(aK1, pa, ka.y);
            fma2(aK0, pb, kb.x); fma2(aK1, pb, kb.y);
        }
        *(ulonglong2*)(g_Q + node * 128 + 4 * l) = make_ulonglong2(aQ0, aQ1);
        *(ulonglong2*)(g_K + node * 128 + 4 * l) = make_ulonglong2(aK0, aK1);
    }
}

// ---------------- edge pass: factored scores + linear aggregation ----------------
// smem: sWef[128][36], sWt[128][36]  ([j][f] layout), stage 8*640 floats
__global__ __launch_bounds__(256) void k_edge(const int* __restrict__ src,
                                              const float* __restrict__ ts,
                                              const float* __restrict__ efeats,
                                              const float* __restrict__ ets,
                                              const float* __restrict__ time_w,
                                              const float* __restrict__ time_b) {
    extern __shared__ float sm[];
    float* sWef = sm;                 // 128*36 = 4608
    float* sWt  = sm + 4608;          // 4608
    float* sAll = sm + 9216;          // 8 * 640 = 5120
    for (int i = threadIdx.x; i < 128 * 32; i += 256) {
        int j = i & 127, f = i >> 7;
        sWef[j * 36 + f] = g_WkT[(64 + f) * 128 + j];
        sWt [j * 36 + f] = g_WkT[(96 + f) * 128 + j];
    }
    __syncthreads();
    int l = threadIdx.x & 31, w = threadIdx.x >> 5;
    int h = l >> 2, sub = l & 3;
    float* stg = sAll + w * 640;
    float tw = __ldg(time_w + l), tb = __ldg(time_b + l);
    int warp = blockIdx.x * 8 + w, stride = gridDim.x * 8;

    for (int node = warp; node < NN; node += stride) {
        __syncwarp();
        int base = g_off[node], deg = g_cnt[node];
        float4 q4 = *(const float4*)(g_Q + node * 128 + 4 * l);
        float qv[4] = {q4.x, q4.y, q4.z, q4.w};
        // prologue: qef[h][f], qt[h][f] slices for this lane (f = sub*8 .. sub*8+7)
        float qef[8], qt[8];
#pragma unroll
        for (int ff = 0; ff < 8; ff++) { qef[ff] = 0.f; qt[ff] = 0.f; }
#pragma unroll
        for (int d = 0; d < 16; d++) {
            int srcl = (l & ~3) | (d >> 2);
            float qd = __shfl_sync(FULLM, qv[d & 3], srcl);
            const float* wr = sWef + (h * 16 + d) * 36 + sub * 8;
            const float* tr = sWt  + (h * 16 + d) * 36 + sub * 8;
            float4 wa = *(const float4*)wr, wb = *(const float4*)(wr + 4);
            float4 ta = *(const float4*)tr, tb4 = *(const float4*)(tr + 4);
            qef[0] = fmaf(qd, wa.x, qef[0]); qef[1] = fmaf(qd, wa.y, qef[1]);
            qef[2] = fmaf(qd, wa.z, qef[2]); qef[3] = fmaf(qd, wa.w, qef[3]);
            qef[4] = fmaf(qd, wb.x, qef[4]); qef[5] = fmaf(qd, wb.y, qef[5]);
            qef[6] = fmaf(qd, wb.z, qef[6]); qef[7] = fmaf(qd, wb.w, qef[7]);
            qt[0] = fmaf(qd, ta.x, qt[0]); qt[1] = fmaf(qd, ta.y, qt[1]);
            qt[2] = fmaf(qd, ta.z, qt[2]); qt[3] = fmaf(qd, ta.w, qt[3]);
            qt[4] = fmaf(qd, tb4.x, qt[4]); qt[5] = fmaf(qd, tb4.y, qt[5]);
            qt[6] = fmaf(qd, tb4.z, qt[6]); qt[7] = fmaf(qd, tb4.w, qt[7]);
        }

        float4 accA = make_float4(0.f, 0.f, 0.f, 0.f);
        float B[8], C[8];
#pragma unroll
        for (int hh = 0; hh < 8; hh++) { B[hh] = 0.f; C[hh] = 0.f; }
        float den = 0.f;

        for (int t0 = 0; t0 < deg; t0 += 4) {
            float4 kh[4];
            float efl[4], ctl[4];
#pragma unroll
            for (int s = 0; s < 4; s++) {
                int t = t0 + s;
                int tc = t < deg ? t : deg - 1;
                int e = g_eidx[base + tc];
                int sn = __ldg(src + e);
                kh[s] = *(const float4*)(g_K + sn * 128 + 4 * l);
                efl[s] = __ldg(efeats + e * 32 + l);
                float td = __ldg(ets + e) - __ldg(ts + sn);
                ctl[s] = cosf(fmaf(td, tw, tb));
                stg[s * 128 + l] = efl[s];
                stg[s * 128 + 32 + l] = ctl[s];
            }
            __syncwarp();
#pragma unroll
            for (int s = 0; s < 4; s++) {
                float p = q4.x * kh[s].x + q4.y * kh[s].y + q4.z * kh[s].z + q4.w * kh[s].w;
                const float* eb = stg + s * 128 + sub * 8;
                const float* cb = stg + s * 128 + 32 + sub * 8;
                float4 ea = *(const float4*)eb, e2 = *(const float4*)(eb + 4);
                float4 ca = *(const float4*)cb, c2 = *(const float4*)(cb + 4);
                p += qef[0] * ea.x + qef[1] * ea.y + qef[2] * ea.z + qef[3] * ea.w
                   + qef[4] * e2.x + qef[5] * e2.y + qef[6] * e2.z + qef[7] * e2.w
                   + qt[0] * ca.x + qt[1] * ca.y + qt[2] * ca.z + qt[3] * ca.w
                   + qt[4] * c2.x + qt[5] * c2.y + qt[6] * c2.z + qt[7] * c2.w;
                p += __shfl_xor_sync(FULLM, p, 1);
                p += __shfl_xor_sync(FULLM, p, 2);
                float eh = (t0 + s < deg) ? expf(p) : 0.f;
                den += eh;
                accA.x = fmaf(eh, kh[s].x, accA.x);
                accA.y = fmaf(eh, kh[s].y, accA.y);
                accA.z = fmaf(eh, kh[s].z, accA.z);
                accA.w = fmaf(eh, kh[s].w, accA.w);
#pragma unroll
                for (int hh = 0; hh < 8; hh++) {
                    float ev = __shfl_sync(FULLM, eh, hh * 4);
                    B[hh] = fmaf(ev, efl[s], B[hh]);
                    C[hh] = fmaf(ev, ctl[s], C[hh]);
                }
            }
            __syncwarp();
        }

        float inv = 1.f / (den * 4.f);   // includes 1/sqrt(D)
        // stage normalized B, C, A
#pragma unroll
        for (int hh = 0; hh < 8; hh++) {
            float iv = __shfl_sync(FULLM, inv, hh * 4);
            stg[hh * 64 + l] = B[hh] * iv;
            stg[hh * 64 + 32 + l] = C[hh] * iv;
        }
        accA.x *= inv; accA.y *= inv; accA.z *= inv; accA.w *= inv;
        *(float4*)(stg + 512 + 4 * l) = accA;
        __syncwarp();
        // epilogue: agg_j = A_j + sum_f Wef[j][f]*B[h(j)][f] + Wt[j][f]*C[h(j)][f]
#pragma unroll
        for (int jj = 0; jj < 4; jj++) {
            int j = l + 32 * jj;
            int hh = j >> 4;
            float a = stg[512 + j];
            const float* bb = stg + hh * 64;
#pragma unroll
            for (int f4 = 0; f4 < 8; f4++) {
                float4 b4 = *(const float4*)(bb + 4 * f4);
                float4 c4 = *(const float4*)(bb + 32 + 4 * f4);
                float4 we = *(const float4*)(sWef + j * 36 + 4 * f4);
                float4 wt4 = *(const float4*)(sWt + j * 36 + 4 * f4);
                a += b4.x * we.x + b4.y * we.y + b4.z * we.z + b4.w * we.w;
                a += c4.x * wt4.x + c4.y * wt4.y + c4.z * wt4.z + c4.w * wt4.w;
            }
            g_agg[node * 128 + j] = a;
        }
    }
}

// ---------------- merge MLP with f32x2 (duplicated weights in smem) ----------------
__global__ __launch_bounds__(512) void k_merge(const float* __restrict__ memory,
                                               const float* __restrict__ b1,
                                               const float* __restrict__ W2,
                                               const float* __restrict__ b2,
                                               float* __restrict__ out) {
    extern __shared__ float sm[];
    float* sX = sm;            // 192*36 = 6912
    float* sU = sm + 6912;     // 8*1024 = 8192 (duplicated weight pairs)
    int tid = threadIdx.x;
    int n0 = blockIdx.x * 32;

    for (int idx = tid; idx < 32 * 192; idx += 512) {
        int n = idx / 192, k = idx % 192;
        int node = n0 + n;
        float v = 0.f;
        if (node < NN) v = (k < 128) ? g_agg[node * 128 + k] : __ldg(memory + node * 64 + (k - 128));
        sX[k * 36 + n] = v;
    }

    int cg = tid & 127, ng = tid >> 7;
    int j0 = cg * 4, m0 = ng * 8;
    unsigned long long acc[4][4];
#pragma unroll
    for (int mp = 0; mp < 4; mp++)
#pragma unroll
        for (int cc = 0; cc < 4; cc++) acc[mp][cc] = 0ULL;

    for (int c = 0; c < 24; c++) {
        __syncthreads();
        for (int idx = tid; idx < 4096; idx += 512) {
            int kk = idx >> 9, j = idx & 511;
            float v = g_W1T[(c * 8 + kk) * 512 + j];
            *(unsigned long long*)(sU + kk * 1024 + 2 * j) = pk2(v, v);
        }
        __syncthreads();
#pragma unroll
        for (int kk = 0; kk < 8; kk++) {
            int k = c * 8 + kk;
            ulonglong2 xa = *(const ulonglong2*)(sX + k * 36 + m0);
            ulonglong2 xb = *(const ulonglong2*)(sX + k * 36 + m0 + 4);
            ulonglong2 wa = *(const ulonglong2*)(sU + kk * 1024 + 2 * j0);
            ulonglong2 wb = *(const ulonglong2*)(sU + kk * 1024 + 2 * j0 + 4);
            fma2(acc[0][0], xa.x, wa.x); fma2(acc[0][1], xa.x, wa.y);
            fma2(acc[0][2], xa.x, wb.x); fma2(acc[0][3], xa.x, wb.y);
            fma2(acc[1][0], xa.y, wa.x); fma2(acc[1][1], xa.y, wa.y);
            fma2(acc[1][2], xa.y, wb.x); fma2(acc[1][3], xa.y, wb.y);
            fma2(acc[2][0], xb.x, wa.x); fma2(acc[2][1], xb.x, wa.y);
            fma2(acc[2][2], xb.x, wb.x); fma2(acc[2][3], xb.x, wb.y);
            fma2(acc[3][0], xb.y, wa.x); fma2(acc[3][1], xb.y, wa.y);
            fma2(acc[3][2], xb.y, wb.x); fma2(acc[3][3], xb.y, wb.y);
        }
    }

    // bias + relu -> hv[8][4]
    float4 bb4 = *(const float4*)(b1 + j0);
    float bm[4] = {bb4.x, bb4.y, bb4.z, bb4.w};
    float hv[8][4];
#pragma unroll
    for (int mp = 0; mp < 4; mp++)
#pragma unroll
        for (int cc = 0; cc < 4; cc++) {
            float2 v = upk2(acc[mp][cc]);
            float lo = v.x + bm[cc], hi = v.y + bm[cc];
            hv[2 * mp][cc] = lo > 0.f ? lo : 0.f;
            hv[2 * mp + 1][cc] = hi > 0.f ? hi : 0.f;
        }

    // second GEMM (out = hid @ W2^T), chunked over j
    int mo_m = tid >> 4, mo_o = tid & 15;
    float* sHc = sU;           // [32][132]
    float* sW2c = sX;          // [16][132]
    unsigned long long pacc = 0ULL;
    for (int c2 = 0; c2 < 4; c2++) {
        __syncthreads();
        if ((cg >> 5) == c2) {
            int jj = (cg & 31) * 4;
#pragma unroll
            for (int mi = 0; mi < 8; mi++)
                *(float4*)(sHc + (m0 + mi) * 132 + jj) =
                    make_float4(hv[mi][0], hv[mi][1], hv[mi][2], hv[mi][3]);
        }
        for (int idx = tid; idx < 16 * 128; idx += 512) {
            int o = idx >> 7, jj = idx & 127;
            sW2c[o * 132 + jj] = __ldg(W2 + o * 512 + c2 * 128 + jj);
        }
        __syncthreads();
#pragma unroll 8
        for (int j4 = 0; j4 < 32; j4++) {
            ulonglong2 h2 = *(const ulonglong2*)(sHc + mo_m * 132 + 4 * j4);
            ulonglong2 w2 = *(const ulonglong2*)(sW2c + mo_o * 132 + 4 * j4);
            fma2(pacc, h2.x, w2.x);
            fma2(pacc, h2.y, w2.y);
        }
    }
    float2 pr = upk2(pacc);
    int node = n0 + mo_m;
    if (node < NN) out[node * 16 + mo_o] = pr.x + pr.y + __ldg(b2 + mo_o);
}

// ---------------- launch ----------------
extern "C" void kernel_launch(void* const* d_in, const int* in_sizes, int n_in,
                              void* d_out, int out_size) {
    const int*   src    = (const int*)d_in[0];
    const int*   dst    = (const int*)d_in[1];
    const float* memory = (const float*)d_in[2];
    const float* ts     = (const float*)d_in[3];
    const float* efeats = (const float*)d_in[4];
    const float* ets    = (const float*)d_in[5];
    const float* Wq     = (const float*)d_in[6];
    const float* Wk     = (const float*)d_in[7];
    const float* W1     = (const float*)d_in[8];
    const float* b1     = (const float*)d_in[9];
    const float* W2     = (const float*)d_in[10];
    const float* b2     = (const float*)d_in[11];
    const float* time_w = (const float*)d_in[12];
    const float* time_b = (const float*)d_in[13];
    float* out = (float*)d_out;

    cudaFuncSetAttribute(k_node,  cudaFuncAttributeMaxDynamicSharedMemorySize, 65536);
    cudaFuncSetAttribute(k_edge,  cudaFuncAttributeMaxDynamicSharedMemorySize, 57344);
    cudaFuncSetAttribute(k_merge, cudaFuncAttributeMaxDynamicSharedMemorySize, 60416);

    k_prep<<<384, 256>>>(Wq, Wk, W1, time_b);
    k_count<<<(EE + 255) / 256, 256>>>(dst);
    k_scan<<<1, 1024>>>();
    k_scatter<<<(EE + 255) / 256, 256>>>(dst);
    k_node<<<592, 256, 65536>>>(memory);
    k_edge<<<592, 256, 57344>>>(src, ts, efeats, ets, time_w, time_b);
    k_merge<<<(NN + 31) / 32, 512, 60416>>>(memory, b1, W2, b2, out);
}